// round 15
// baseline (speedup 1.0000x reference)
#include <cuda_runtime.h>

#define NUM_NET 2
#define V 100000
#define D 128
#define B 4096
#define K 5
#define NS 10

#define NTHREADS 256
#define WPB 8
#define NEIGH_BLOCKS 4096                  // 32768 warps: 4 per (i,b), table-phased
#define NODE_BLOCKS  2048                  // 16384 warps: 1 per (i,b,m)
#define NBLOCKS (NEIGH_BLOCKS + NODE_BLOCKS)  // 6144, interleaved 2 neigh : 1 node
#define NPART NBLOCKS

#define FULLMASK 0xffffffffu

__device__ float g_part[NPART];
__device__ int   g_count = 0;

__device__ __forceinline__ float logsig_fast(float x) {
    // log(sigmoid(x)) = min(x,0) - log(1 + exp(-|x|)); fast-math (err ~1e-6 vs 1e-3 budget)
    return fminf(x, 0.0f) - __logf(1.0f + __expf(-fabsf(x)));
}

__device__ __forceinline__ float dot4(float4 a, float4 b) {
    return fmaf(a.x, b.x, fmaf(a.y, b.y, fmaf(a.z, b.z, a.w * b.w)));
}

// Load an index list (M <= 32) into lane-distributed registers: one coalesced LDG.
__device__ __forceinline__ int load_idx(const int* __restrict__ idx, int M, int lane) {
    return __ldg(idx + (lane < M ? lane : 0));
}

// Sum of logsig(sign*(row . ne)) over M rows whose indices live in myidx
// (lane-distributed). Indices come via SHFL (4 cyc) instead of an L2-latency
// load -> per-batch serial chain drops from ~750 to ~500 cyc.
template<bool NEG>
__device__ __forceinline__ float rows_reg5(const float* __restrict__ tab,
                                           int myidx, int M, float4 ne, int lane) {
    float a = 0.0f;
    for (int m = 0; m < M; m += 5) {
        float4 c[5];
        #pragma unroll
        for (int u = 0; u < 5; u++) {
            int id = __shfl_sync(FULLMASK, myidx, m + u);
            c[u] = __ldg(reinterpret_cast<const float4*>(tab + (size_t)id * D) + lane);
        }
        float s[5];
        #pragma unroll
        for (int u = 0; u < 5; u++) s[u] = dot4(ne, c[u]);
        #pragma unroll
        for (int off = 16; off; off >>= 1) {
            #pragma unroll
            for (int u = 0; u < 5; u++)
                s[u] += __shfl_xor_sync(FULLMASK, s[u], off);
        }
        #pragma unroll
        for (int u = 0; u < 5; u++) a += logsig_fast(NEG ? -s[u] : s[u]);
    }
    return a;
}

__device__ __forceinline__ float pos2(const float* __restrict__ tab, int i0, int i1,
                                      float4 ne, int lane) {
    float4 c0 = __ldg(reinterpret_cast<const float4*>(tab + (size_t)i0 * D) + lane);
    float4 c1 = __ldg(reinterpret_cast<const float4*>(tab + (size_t)i1 * D) + lane);
    float s0 = dot4(ne, c0), s1 = dot4(ne, c1);
    #pragma unroll
    for (int off = 16; off; off >>= 1) {
        s0 += __shfl_xor_sync(FULLMASK, s0, off);
        s1 += __shfl_xor_sync(FULLMASK, s1, off);
    }
    return logsig_fast(s0) + logsig_fast(s1);
}

__device__ __forceinline__ float pos1(const float* __restrict__ tab, int i0,
                                      float4 ne, int lane) {
    float4 c0 = __ldg(reinterpret_cast<const float4*>(tab + (size_t)i0 * D) + lane);
    float s0 = dot4(ne, c0);
    #pragma unroll
    for (int off = 16; off; off >>= 1)
        s0 += __shfl_xor_sync(FULLMASK, s0, off);
    return logsig_fast(s0);
}

__global__ void __launch_bounds__(NTHREADS)
loss_kernel(const float* __restrict__ node_tables,
            const float* __restrict__ neigh_tables,
            const int* __restrict__ nodes_idx,
            const int* __restrict__ neigh_idx,
            const int* __restrict__ role_idx,
            const int* __restrict__ neg_main,
            const int* __restrict__ neg_node,
            const int* __restrict__ neg_cross,
            const int* __restrict__ neg_role,
            float* __restrict__ out) {
    const int lane = threadIdx.x & 31;
    const int wid  = threadIdx.x >> 5;
    const size_t VD = (size_t)V * D;

    const float CB = 1.0f / (10.0f * (float)B);
    const float WH = 0.1f;

    // interleave: per block-trio, 2 neigh blocks (heavy) + 1 node block (light)
    const int trio = blockIdx.x / 3;
    const int rsel = blockIdx.x - trio * 3;

    float acc = 0.0f;
    int slot;

    if (rsel < 2) {
        // ================= neigh work (t1, t3) =================
        const int nb = trio * 2 + rsel;            // 0 .. 4095
        slot = nb;
        const int gw = nb * WPB + wid;             // 0 .. 32767

        const int g   = gw >> 14;                  // target neigh table
        const int r   = gw & 16383;
        const int b   = r >> 2;
        const int sub = r & 3;

        const float* gt = neigh_tables + (size_t)g * VD;

        if (sub < 2) {
            // main SGNS of view i=g (weight 1)
            const int nid = __ldg(nodes_idx + g * B + b);
            const int* nm = neg_main + (size_t)(g * B + b) * (K * NS);
            if (sub == 0) {
                const int pidx = load_idx(neigh_idx + (g * B + b) * K, K, lane);
                const int nidx = load_idx(nm, 25, lane);
                const float4 ne = __ldg(reinterpret_cast<const float4*>(
                    node_tables + (size_t)g * VD + (size_t)nid * D) + lane);
                acc += rows_reg5<false>(gt, pidx, K, ne, lane) * (-CB / (float)K);
                acc += rows_reg5<true>(gt, nidx, 25, ne, lane) * (-CB);
            } else {
                const int nidx = load_idx(nm + 25, 25, lane);
                const float4 ne = __ldg(reinterpret_cast<const float4*>(
                    node_tables + (size_t)g * VD + (size_t)nid * D) + lane);
                acc += rows_reg5<true>(gt, nidx, 25, ne, lane) * (-CB);
            }
        } else {
            // cross neighbor loss of view i=1-g with j=g (weight HYP2)
            const int i = 1 - g;
            const int nid = __ldg(nodes_idx + i * B + b);
            const int* nc = neg_cross + (size_t)((i * NUM_NET + g) * B + b) * (K * NS);
            if (sub == 2) {
                const int pidx = load_idx(neigh_idx + (i * B + b) * K, K, lane);
                const int nidx = load_idx(nc, 25, lane);
                const float4 ne = __ldg(reinterpret_cast<const float4*>(
                    node_tables + (size_t)i * VD + (size_t)nid * D) + lane);
                acc += rows_reg5<false>(gt, pidx, K, ne, lane) * (-WH * CB / (float)K);
                acc += rows_reg5<true>(gt, nidx, 25, ne, lane) * (-WH * CB);
            } else {
                const int nidx = load_idx(nc + 25, 25, lane);
                const float4 ne = __ldg(reinterpret_cast<const float4*>(
                    node_tables + (size_t)i * VD + (size_t)nid * D) + lane);
                acc += rows_reg5<true>(gt, nidx, 25, ne, lane) * (-WH * CB);
            }
        }
    } else {
        // ================= node work (t2, roles) =================
        const int qb = trio;                       // 0 .. 2047
        slot = NEIGH_BLOCKS + qb;
        const int gw = qb * WPB + wid;             // 0 .. 16383

        const int m = gw >> 13;                    // target node table
        const int r = gw & 8191;
        const int i = r >> 12;
        const int b = r & 4095;

        const float* nt = node_tables + (size_t)m * VD;

        const int nid = __ldg(nodes_idx + i * B + b);
        const int rp  = __ldg(role_idx + (i * NUM_NET + m) * B + b);
        const int ridx = load_idx(neg_role + (size_t)((i * NUM_NET + m) * B + b) * NS, NS, lane);

        const float w = -WH * CB;

        if (m != i) {
            const int tidx = load_idx(neg_node + (size_t)((i * NUM_NET + m) * B + b) * NS, NS, lane);
            const float4 ne = __ldg(reinterpret_cast<const float4*>(
                node_tables + (size_t)i * VD + (size_t)nid * D) + lane);
            // t2 (pos=nid row in nt_m, 10 negs) + role j2=m (pos + 10 negs)
            acc += pos2(nt, nid, rp, ne, lane) * w;
            acc += rows_reg5<true>(nt, tidx, NS, ne, lane) * w;
            acc += rows_reg5<true>(nt, ridx, NS, ne, lane) * w;
        } else {
            const float4 ne = __ldg(reinterpret_cast<const float4*>(
                node_tables + (size_t)i * VD + (size_t)nid * D) + lane);
            // role j2=m=i only
            acc += pos1(nt, rp, ne, lane) * w;
            acc += rows_reg5<true>(nt, ridx, NS, ne, lane) * w;
        }
    }

    __shared__ float sacc[WPB];
    __shared__ int s_last;
    if (lane == 0) sacc[wid] = acc;
    __syncthreads();
    if (threadIdx.x == 0) {
        float t = 0.0f;
        #pragma unroll
        for (int w = 0; w < WPB; w++) t += sacc[w];
        g_part[slot] = t;             // always written: no zero-init needed
        __threadfence();
        int c = atomicAdd(&g_count, 1);
        s_last = (c == NBLOCKS - 1);
    }
    __syncthreads();

    // the last block to arrive reduces all partials; fixed read order -> deterministic
    if (s_last) {
        __threadfence();              // acquire: see all g_part writes
        __shared__ double sh[WPB];
        double t = 0.0;
        for (int k2 = threadIdx.x; k2 < NPART; k2 += NTHREADS)
            t += (double)g_part[k2];
        #pragma unroll
        for (int off = 16; off; off >>= 1)
            t += __shfl_xor_sync(FULLMASK, t, off);
        if (lane == 0) sh[wid] = t;
        __syncthreads();
        if (threadIdx.x == 0) {
            double v = 0.0;
            #pragma unroll
            for (int ww = 0; ww < WPB; ww++) v += sh[ww];
            out[0] = (float)v;
            g_count = 0;              // reset for next graph replay
        }
    }
}

extern "C" void kernel_launch(void* const* d_in, const int* in_sizes, int n_in,
                              void* d_out, int out_size) {
    const float* node_tables  = (const float*)d_in[0];
    const float* neigh_tables = (const float*)d_in[1];
    const int*   nodes_idx    = (const int*)d_in[2];
    const int*   neigh_idx    = (const int*)d_in[3];
    const int*   role_idx     = (const int*)d_in[4];
    const int*   neg_main     = (const int*)d_in[5];
    const int*   neg_node     = (const int*)d_in[6];
    const int*   neg_cross    = (const int*)d_in[7];
    const int*   neg_role     = (const int*)d_in[8];

    (void)in_sizes; (void)n_in; (void)out_size;

    loss_kernel<<<NBLOCKS, NTHREADS>>>(node_tables, neigh_tables, nodes_idx,
                                       neigh_idx, role_idx, neg_main,
                                       neg_node, neg_cross, neg_role,
                                       (float*)d_out);
}

// round 16
// speedup vs baseline: 1.0264x; 1.0264x over previous
#include <cuda_runtime.h>

#define NUM_NET 2
#define V 100000
#define D 128
#define B 4096
#define K 5
#define NS 10

#define NTHREADS 256
#define WPB 8
#define NEIGH_BLOCKS 4096                  // 32768 warps: 4 per (i,b), table-phased
#define NODE_BLOCKS  2048                  // 16384 warps: 1 per (i,b,m)
#define NBLOCKS (NEIGH_BLOCKS + NODE_BLOCKS)  // 6144, interleaved 2 neigh : 1 node
#define NPART NBLOCKS

#define FULLMASK 0xffffffffu

__device__ float g_part[NPART];
__device__ int   g_count = 0;

__device__ __forceinline__ float logsig_fast(float x) {
    // log(sigmoid(x)) = min(x,0) - log(1 + exp(-|x|)); fast-math (err ~1e-6 vs 1e-3 budget)
    return fminf(x, 0.0f) - __logf(1.0f + __expf(-fabsf(x)));
}

__device__ __forceinline__ float dot4(float4 a, float4 b) {
    return fmaf(a.x, b.x, fmaf(a.y, b.y, fmaf(a.z, b.z, a.w * b.w)));
}

// Load an index list (M <= 32) into lane-distributed registers: one coalesced LDG.
__device__ __forceinline__ int load_idx(const int* __restrict__ idx, int M, int lane) {
    return __ldg(idx + (lane < M ? lane : 0));
}

// Sum of logsig(sign*(row . ne)) over M rows whose indices live in myidx
// (lane-distributed, fetched via SHFL: 4 cyc vs L2-latency idx loads).
template<bool NEG>
__device__ __forceinline__ float rows_reg5(const float* __restrict__ tab,
                                           int myidx, int M, float4 ne, int lane) {
    float a = 0.0f;
    for (int m = 0; m < M; m += 5) {
        float4 c[5];
        #pragma unroll
        for (int u = 0; u < 5; u++) {
            int id = __shfl_sync(FULLMASK, myidx, m + u);
            c[u] = __ldg(reinterpret_cast<const float4*>(tab + (size_t)id * D) + lane);
        }
        float s[5];
        #pragma unroll
        for (int u = 0; u < 5; u++) s[u] = dot4(ne, c[u]);
        #pragma unroll
        for (int off = 16; off; off >>= 1) {
            #pragma unroll
            for (int u = 0; u < 5; u++)
                s[u] += __shfl_xor_sync(FULLMASK, s[u], off);
        }
        #pragma unroll
        for (int u = 0; u < 5; u++) a += logsig_fast(NEG ? -s[u] : s[u]);
    }
    return a;
}

__device__ __forceinline__ float pos2(const float* __restrict__ tab, int i0, int i1,
                                      float4 ne, int lane) {
    float4 c0 = __ldg(reinterpret_cast<const float4*>(tab + (size_t)i0 * D) + lane);
    float4 c1 = __ldg(reinterpret_cast<const float4*>(tab + (size_t)i1 * D) + lane);
    float s0 = dot4(ne, c0), s1 = dot4(ne, c1);
    #pragma unroll
    for (int off = 16; off; off >>= 1) {
        s0 += __shfl_xor_sync(FULLMASK, s0, off);
        s1 += __shfl_xor_sync(FULLMASK, s1, off);
    }
    return logsig_fast(s0) + logsig_fast(s1);
}

__device__ __forceinline__ float pos1(const float* __restrict__ tab, int i0,
                                      float4 ne, int lane) {
    float4 c0 = __ldg(reinterpret_cast<const float4*>(tab + (size_t)i0 * D) + lane);
    float s0 = dot4(ne, c0);
    #pragma unroll
    for (int off = 16; off; off >>= 1)
        s0 += __shfl_xor_sync(FULLMASK, s0, off);
    return logsig_fast(s0);
}

__global__ void __launch_bounds__(NTHREADS, 8)   // force 32 regs -> 64 warps/SM
loss_kernel(const float* __restrict__ node_tables,
            const float* __restrict__ neigh_tables,
            const int* __restrict__ nodes_idx,
            const int* __restrict__ neigh_idx,
            const int* __restrict__ role_idx,
            const int* __restrict__ neg_main,
            const int* __restrict__ neg_node,
            const int* __restrict__ neg_cross,
            const int* __restrict__ neg_role,
            float* __restrict__ out) {
    const int lane = threadIdx.x & 31;
    const int wid  = threadIdx.x >> 5;
    const size_t VD = (size_t)V * D;

    const float CB = 1.0f / (10.0f * (float)B);
    const float WH = 0.1f;

    // interleave: per block-trio, 2 neigh blocks (heavy) + 1 node block (light)
    const int trio = blockIdx.x / 3;
    const int rsel = blockIdx.x - trio * 3;

    float acc = 0.0f;
    int slot;

    if (rsel < 2) {
        // ================= neigh work (t1, t3) =================
        const int nb = trio * 2 + rsel;            // 0 .. 4095
        slot = nb;
        const int gw = nb * WPB + wid;             // 0 .. 32767

        const int g   = gw >> 14;                  // target neigh table
        const int r   = gw & 16383;
        const int b   = r >> 2;
        const int sub = r & 3;

        const float* gt = neigh_tables + (size_t)g * VD;

        if (sub < 2) {
            // main SGNS of view i=g (weight 1)
            const int nid = __ldg(nodes_idx + g * B + b);
            const float4 ne = __ldg(reinterpret_cast<const float4*>(
                node_tables + (size_t)g * VD + (size_t)nid * D) + lane);
            const int* nm = neg_main + (size_t)(g * B + b) * (K * NS);
            if (sub == 0) {
                {   // positive list first; its idx reg dies before the neg list loads
                    const int pidx = load_idx(neigh_idx + (g * B + b) * K, K, lane);
                    acc += rows_reg5<false>(gt, pidx, K, ne, lane) * (-CB / (float)K);
                }
                const int nidx = load_idx(nm, 25, lane);
                acc += rows_reg5<true>(gt, nidx, 25, ne, lane) * (-CB);
            } else {
                const int nidx = load_idx(nm + 25, 25, lane);
                acc += rows_reg5<true>(gt, nidx, 25, ne, lane) * (-CB);
            }
        } else {
            // cross neighbor loss of view i=1-g with j=g (weight HYP2)
            const int i = 1 - g;
            const int nid = __ldg(nodes_idx + i * B + b);
            const float4 ne = __ldg(reinterpret_cast<const float4*>(
                node_tables + (size_t)i * VD + (size_t)nid * D) + lane);
            const int* nc = neg_cross + (size_t)((i * NUM_NET + g) * B + b) * (K * NS);
            if (sub == 2) {
                {
                    const int pidx = load_idx(neigh_idx + (i * B + b) * K, K, lane);
                    acc += rows_reg5<false>(gt, pidx, K, ne, lane) * (-WH * CB / (float)K);
                }
                const int nidx = load_idx(nc, 25, lane);
                acc += rows_reg5<true>(gt, nidx, 25, ne, lane) * (-WH * CB);
            } else {
                const int nidx = load_idx(nc + 25, 25, lane);
                acc += rows_reg5<true>(gt, nidx, 25, ne, lane) * (-WH * CB);
            }
        }
    } else {
        // ================= node work (t2, roles) =================
        const int qb = trio;                       // 0 .. 2047
        slot = NEIGH_BLOCKS + qb;
        const int gw = qb * WPB + wid;             // 0 .. 16383

        const int m = gw >> 13;                    // target node table
        const int r = gw & 8191;
        const int i = r >> 12;
        const int b = r & 4095;

        const float* nt = node_tables + (size_t)m * VD;

        const int nid = __ldg(nodes_idx + i * B + b);
        const float4 ne = __ldg(reinterpret_cast<const float4*>(
            node_tables + (size_t)i * VD + (size_t)nid * D) + lane);

        const float w = -WH * CB;
        const int rp = __ldg(role_idx + (i * NUM_NET + m) * B + b);

        if (m != i) {
            // t2 (pos=nid row in nt_m, 10 negs) + role j2=m (pos + 10 negs)
            acc += pos2(nt, nid, rp, ne, lane) * w;
            {
                const int tidx = load_idx(neg_node + (size_t)((i * NUM_NET + m) * B + b) * NS, NS, lane);
                acc += rows_reg5<true>(nt, tidx, NS, ne, lane) * w;
            }
            const int ridx = load_idx(neg_role + (size_t)((i * NUM_NET + m) * B + b) * NS, NS, lane);
            acc += rows_reg5<true>(nt, ridx, NS, ne, lane) * w;
        } else {
            // role j2=m=i only
            acc += pos1(nt, rp, ne, lane) * w;
            const int ridx = load_idx(neg_role + (size_t)((i * NUM_NET + m) * B + b) * NS, NS, lane);
            acc += rows_reg5<true>(nt, ridx, NS, ne, lane) * w;
        }
    }

    __shared__ float sacc[WPB];
    __shared__ int s_last;
    if (lane == 0) sacc[wid] = acc;
    __syncthreads();
    if (threadIdx.x == 0) {
        float t = 0.0f;
        #pragma unroll
        for (int w = 0; w < WPB; w++) t += sacc[w];
        g_part[slot] = t;             // always written: no zero-init needed
        __threadfence();
        int c = atomicAdd(&g_count, 1);
        s_last = (c == NBLOCKS - 1);
    }
    __syncthreads();

    // the last block to arrive reduces all partials; fixed read order -> deterministic
    if (s_last) {
        __threadfence();              // acquire: see all g_part writes
        __shared__ double sh[WPB];
        double t = 0.0;
        for (int k2 = threadIdx.x; k2 < NPART; k2 += NTHREADS)
            t += (double)g_part[k2];
        #pragma unroll
        for (int off = 16; off; off >>= 1)
            t += __shfl_xor_sync(FULLMASK, t, off);
        if (lane == 0) sh[wid] = t;
        __syncthreads();
        if (threadIdx.x == 0) {
            double v = 0.0;
            #pragma unroll
            for (int ww = 0; ww < WPB; ww++) v += sh[ww];
            out[0] = (float)v;
            g_count = 0;              // reset for next graph replay
        }
    }
}

extern "C" void kernel_launch(void* const* d_in, const int* in_sizes, int n_in,
                              void* d_out, int out_size) {
    const float* node_tables  = (const float*)d_in[0];
    const float* neigh_tables = (const float*)d_in[1];
    const int*   nodes_idx    = (const int*)d_in[2];
    const int*   neigh_idx    = (const int*)d_in[3];
    const int*   role_idx     = (const int*)d_in[4];
    const int*   neg_main     = (const int*)d_in[5];
    const int*   neg_node     = (const int*)d_in[6];
    const int*   neg_cross    = (const int*)d_in[7];
    const int*   neg_role     = (const int*)d_in[8];

    (void)in_sizes; (void)n_in; (void)out_size;

    loss_kernel<<<NBLOCKS, NTHREADS>>>(node_tables, neigh_tables, nodes_idx,
                                       neigh_idx, role_idx, neg_main,
                                       neg_node, neg_cross, neg_role,
                                       (float*)d_out);
}

// round 17
// speedup vs baseline: 1.0406x; 1.0138x over previous
#include <cuda_runtime.h>

#define NUM_NET 2
#define V 100000
#define D 128
#define B 4096
#define K 5
#define NS 10

#define NTHREADS 256
#define WPB 8
#define NEIGH_BLOCKS 4096                  // 32768 warps: 4 per (i,b), table-phased
#define NODE_BLOCKS  2048                  // 16384 warps: 1 per (i,b,m)
#define NBLOCKS (NEIGH_BLOCKS + NODE_BLOCKS)  // 6144, interleaved 2 neigh : 1 node
#define NPART NBLOCKS

__device__ float g_part[NPART];
__device__ int   g_count = 0;

__device__ __forceinline__ float logsig_fast(float x) {
    // log(sigmoid(x)) = min(x,0) - log(1 + exp(-|x|)); fast-math (err ~1e-6 vs 1e-3 budget)
    return fminf(x, 0.0f) - __logf(1.0f + __expf(-fabsf(x)));
}

__device__ __forceinline__ float dot4(float4 a, float4 b) {
    return fmaf(a.x, b.x, fmaf(a.y, b.y, fmaf(a.z, b.z, a.w * b.w)));
}

// Streaming row gather: L1-bypass (.cg). Random 512B rows have ~0% L1 hit
// rate; skipping L1 fill/tag removes load from the busiest per-SM pipe.
__device__ __forceinline__ float4 row_ldcg(const float* __restrict__ tab, int id, int lane) {
    return __ldcg(reinterpret_cast<const float4*>(tab + (size_t)id * D) + lane);
}

// Sum of logsig(sign*(row . ne)) over M rows, 5 independent chains per batch.
// The proven 32-reg shape; row gathers bypass L1.
template<bool NEG>
__device__ __forceinline__ float rows_sum5(const float* __restrict__ tab,
                                           const int* __restrict__ idx,
                                           int M, float4 ne, int lane) {
    float a = 0.0f;
    for (int m = 0; m < M; m += 5) {
        float4 c[5];
        #pragma unroll
        for (int u = 0; u < 5; u++) {
            int id = __ldg(idx + m + u);       // warp-uniform, L1-friendly
            c[u] = row_ldcg(tab, id, lane);
        }
        float s[5];
        #pragma unroll
        for (int u = 0; u < 5; u++) s[u] = dot4(ne, c[u]);
        #pragma unroll
        for (int off = 16; off; off >>= 1) {
            #pragma unroll
            for (int u = 0; u < 5; u++)
                s[u] += __shfl_xor_sync(0xffffffffu, s[u], off);
        }
        #pragma unroll
        for (int u = 0; u < 5; u++) a += logsig_fast(NEG ? -s[u] : s[u]);
    }
    return a;
}

__device__ __forceinline__ float pos2(const float* __restrict__ tab, int i0, int i1,
                                      float4 ne, int lane) {
    float4 c0 = row_ldcg(tab, i0, lane);
    float4 c1 = row_ldcg(tab, i1, lane);
    float s0 = dot4(ne, c0), s1 = dot4(ne, c1);
    #pragma unroll
    for (int off = 16; off; off >>= 1) {
        s0 += __shfl_xor_sync(0xffffffffu, s0, off);
        s1 += __shfl_xor_sync(0xffffffffu, s1, off);
    }
    return logsig_fast(s0) + logsig_fast(s1);
}

__device__ __forceinline__ float pos1(const float* __restrict__ tab, int i0,
                                      float4 ne, int lane) {
    float4 c0 = row_ldcg(tab, i0, lane);
    float s0 = dot4(ne, c0);
    #pragma unroll
    for (int off = 16; off; off >>= 1)
        s0 += __shfl_xor_sync(0xffffffffu, s0, off);
    return logsig_fast(s0);
}

__global__ void __launch_bounds__(NTHREADS)
loss_kernel(const float* __restrict__ node_tables,
            const float* __restrict__ neigh_tables,
            const int* __restrict__ nodes_idx,
            const int* __restrict__ neigh_idx,
            const int* __restrict__ role_idx,
            const int* __restrict__ neg_main,
            const int* __restrict__ neg_node,
            const int* __restrict__ neg_cross,
            const int* __restrict__ neg_role,
            float* __restrict__ out) {
    const int lane = threadIdx.x & 31;
    const int wid  = threadIdx.x >> 5;
    const size_t VD = (size_t)V * D;

    const float CB = 1.0f / (10.0f * (float)B);
    const float WH = 0.1f;

    // interleave: per block-trio, 2 neigh blocks (heavy) + 1 node block (light)
    const int trio = blockIdx.x / 3;
    const int rsel = blockIdx.x - trio * 3;

    float acc = 0.0f;
    int slot;

    if (rsel < 2) {
        // ================= neigh work (t1, t3) =================
        const int nb = trio * 2 + rsel;            // 0 .. 4095
        slot = nb;
        const int gw = nb * WPB + wid;             // 0 .. 32767

        const int g   = gw >> 14;                  // target neigh table
        const int r   = gw & 16383;
        const int b   = r >> 2;
        const int sub = r & 3;

        const float* gt = neigh_tables + (size_t)g * VD;

        if (sub < 2) {
            // main SGNS of view i=g (weight 1)
            const int nid = __ldg(nodes_idx + g * B + b);
            const float4 ne = __ldg(reinterpret_cast<const float4*>(
                node_tables + (size_t)g * VD + (size_t)nid * D) + lane);
            const int* nm = neg_main + (size_t)(g * B + b) * (K * NS);
            if (sub == 0) {
                acc += rows_sum5<false>(gt, neigh_idx + (g * B + b) * K, K, ne, lane) * (-CB / (float)K);
                acc += rows_sum5<true>(gt, nm, 25, ne, lane) * (-CB);
            } else {
                acc += rows_sum5<true>(gt, nm + 25, 25, ne, lane) * (-CB);
            }
        } else {
            // cross neighbor loss of view i=1-g with j=g (weight HYP2)
            const int i = 1 - g;
            const int nid = __ldg(nodes_idx + i * B + b);
            const float4 ne = __ldg(reinterpret_cast<const float4*>(
                node_tables + (size_t)i * VD + (size_t)nid * D) + lane);
            const int* nc = neg_cross + (size_t)((i * NUM_NET + g) * B + b) * (K * NS);
            if (sub == 2) {
                acc += rows_sum5<false>(gt, neigh_idx + (i * B + b) * K, K, ne, lane) * (-WH * CB / (float)K);
                acc += rows_sum5<true>(gt, nc, 25, ne, lane) * (-WH * CB);
            } else {
                acc += rows_sum5<true>(gt, nc + 25, 25, ne, lane) * (-WH * CB);
            }
        }
    } else {
        // ================= node work (t2, roles) =================
        const int qb = trio;                       // 0 .. 2047
        slot = NEIGH_BLOCKS + qb;
        const int gw = qb * WPB + wid;             // 0 .. 16383

        const int m = gw >> 13;                    // target node table
        const int r = gw & 8191;
        const int i = r >> 12;
        const int b = r & 4095;

        const float* nt = node_tables + (size_t)m * VD;

        const int nid = __ldg(nodes_idx + i * B + b);
        const float4 ne = __ldg(reinterpret_cast<const float4*>(
            node_tables + (size_t)i * VD + (size_t)nid * D) + lane);

        const float w = -WH * CB;
        const int* nr = neg_role + (size_t)((i * NUM_NET + m) * B + b) * NS;
        const int rp  = __ldg(role_idx + (i * NUM_NET + m) * B + b);

        if (m != i) {
            // t2 (pos=nid row in nt_m, 10 negs) + role j2=m (pos + 10 negs)
            acc += pos2(nt, nid, rp, ne, lane) * w;
            acc += rows_sum5<true>(nt, neg_node + (size_t)((i * NUM_NET + m) * B + b) * NS, NS, ne, lane) * w;
            acc += rows_sum5<true>(nt, nr, NS, ne, lane) * w;
        } else {
            // role j2=m=i only
            acc += pos1(nt, rp, ne, lane) * w;
            acc += rows_sum5<true>(nt, nr, NS, ne, lane) * w;
        }
    }

    __shared__ float sacc[WPB];
    __shared__ int s_last;
    if (lane == 0) sacc[wid] = acc;
    __syncthreads();
    if (threadIdx.x == 0) {
        float t = 0.0f;
        #pragma unroll
        for (int w = 0; w < WPB; w++) t += sacc[w];
        g_part[slot] = t;             // always written: no zero-init needed
        __threadfence();
        int c = atomicAdd(&g_count, 1);
        s_last = (c == NBLOCKS - 1);
    }
    __syncthreads();

    // the last block to arrive reduces all partials; fixed read order -> deterministic
    if (s_last) {
        __threadfence();              // acquire: see all g_part writes
        __shared__ double sh[WPB];
        double t = 0.0;
        for (int k2 = threadIdx.x; k2 < NPART; k2 += NTHREADS)
            t += (double)g_part[k2];
        #pragma unroll
        for (int off = 16; off; off >>= 1)
            t += __shfl_xor_sync(0xffffffffu, t, off);
        if (lane == 0) sh[wid] = t;
        __syncthreads();
        if (threadIdx.x == 0) {
            double v = 0.0;
            #pragma unroll
            for (int ww = 0; ww < WPB; ww++) v += sh[ww];
            out[0] = (float)v;
            g_count = 0;              // reset for next graph replay
        }
    }
}

extern "C" void kernel_launch(void* const* d_in, const int* in_sizes, int n_in,
                              void* d_out, int out_size) {
    const float* node_tables  = (const float*)d_in[0];
    const float* neigh_tables = (const float*)d_in[1];
    const int*   nodes_idx    = (const int*)d_in[2];
    const int*   neigh_idx    = (const int*)d_in[3];
    const int*   role_idx     = (const int*)d_in[4];
    const int*   neg_main     = (const int*)d_in[5];
    const int*   neg_node     = (const int*)d_in[6];
    const int*   neg_cross    = (const int*)d_in[7];
    const int*   neg_role     = (const int*)d_in[8];

    (void)in_sizes; (void)n_in; (void)out_size;

    loss_kernel<<<NBLOCKS, NTHREADS>>>(node_tables, neigh_tables, nodes_idx,
                                       neigh_idx, role_idx, neg_main,
                                       neg_node, neg_cross, neg_role,
                                       (float*)d_out);
}